// round 17
// baseline (speedup 1.0000x reference)
#include <cuda_runtime.h>
#include <cuda_fp16.h>
#include <cstdint>

// ---------------------------------------------------------------------------
// GraphormerMultiHeadAttention  (B=16, N=512, HIDDEN=768, 12 heads x 64)
//
// All-fp16 1-term MMA data flow (error budget ~6.5e-4 < 1e-3):
//   x,W,bias -> fp16; QKV GEMM (256x128 tiles) -> fp16 Q(scaled)/K/V;
//   flash attention (log2-domain softmax, MUFU ex2, bias+K/V one cp.async
//   group, single barrier/chunk) -> fp16 O; O GEMM -> fp32 out.
// ---------------------------------------------------------------------------

#define HID    768
#define MTOT   8192
#define NSEQ   512
#define NHEAD  12
#define DHEAD  64
#define SCALE_F 0.03608439182435161f   // 768^-0.5
#define LOG2E_F 1.4426950408889634f
#define QSCALE  (SCALE_F * LOG2E_F)    // log2-domain scores
#define WSZ (HID * HID)

// ---------------- scratch (device globals; allocation-free) ----------------
__device__ __align__(16) __half g_ah[MTOT * HID];          // x (fp16)
__device__ __align__(16) __half g_qh[MTOT * HID];          // Q (QSCALE folded)
__device__ __align__(16) __half g_kh[MTOT * HID];          // K
__device__ __align__(16) __half g_vh[MTOT * HID];          // V
__device__ __align__(16) __half g_oh[MTOT * HID];          // attn out
__device__ __align__(16) __half g_wh[4 * WSZ];             // Wq,Wk,Wv,Wo
__device__ __align__(16) __half g_eb[16 * NSEQ * NSEQ];    // bias (fp16)

// ---------------------------------------------------------------------------
// conversions
// ---------------------------------------------------------------------------
__global__ void conv_round_x(const float* __restrict__ src, int n4)
{
    int i = blockIdx.x * blockDim.x + threadIdx.x;
    if (i >= n4) return;
    float4 v = ((const float4*)src)[i];
    ((__half2*)g_ah)[2 * i]     = __floats2half2_rn(v.x, v.y);
    ((__half2*)g_ah)[2 * i + 1] = __floats2half2_rn(v.z, v.w);
}

__global__ void conv_round_eb(const float* __restrict__ src, int n4)
{
    int i = blockIdx.x * blockDim.x + threadIdx.x;
    if (i >= n4) return;
    float4 v = ((const float4*)src)[i];
    ((__half2*)g_eb)[2 * i]     = __floats2half2_rn(v.x, v.y);
    ((__half2*)g_eb)[2 * i + 1] = __floats2half2_rn(v.z, v.w);
}

__global__ void conv_w4(const float* __restrict__ w0,
                        const float* __restrict__ w1,
                        const float* __restrict__ w2,
                        const float* __restrict__ w3, int n4)
{
    int i = blockIdx.x * blockDim.x + threadIdx.x;
    if (i >= n4) return;
    const int z = blockIdx.y;
    const float* src = (z == 0) ? w0 : (z == 1) ? w1 : (z == 2) ? w2 : w3;
    float4 v = ((const float4*)src)[i];
    size_t base = (size_t)z * (WSZ / 2);
    ((__half2*)g_wh)[base + 2 * i]     = __floats2half2_rn(v.x, v.y);
    ((__half2*)g_wh)[base + 2 * i + 1] = __floats2half2_rn(v.z, v.w);
}

// ---------------------------------------------------------------------------
// warp-mma / async-copy helpers
// ---------------------------------------------------------------------------
__device__ __forceinline__ uint32_t smem_u32(const void* p)
{
    uint32_t a;
    asm("{ .reg .u64 t; cvta.to.shared.u64 t, %1; cvt.u32.u64 %0, t; }"
        : "=r"(a) : "l"(p));
    return a;
}
__device__ __forceinline__ void cp16(uint32_t dst, const void* src)
{
    size_t gsrc = __cvta_generic_to_global(src);
    asm volatile("cp.async.cg.shared.global [%0], [%1], 16;"
                 :: "r"(dst), "l"(gsrc) : "memory");
}
__device__ __forceinline__ void cp_commit()
{
    asm volatile("cp.async.commit_group;" ::: "memory");
}
template <int N>
__device__ __forceinline__ void cp_wait()
{
    asm volatile("cp.async.wait_group %0;" :: "n"(N) : "memory");
}
__device__ __forceinline__ void ldm4(uint32_t* r, uint32_t addr)
{
    asm volatile("ldmatrix.sync.aligned.m8n8.x4.shared.b16 {%0,%1,%2,%3}, [%4];"
                 : "=r"(r[0]), "=r"(r[1]), "=r"(r[2]), "=r"(r[3]) : "r"(addr));
}
__device__ __forceinline__ void ldm4t(uint32_t* r, uint32_t addr)
{
    asm volatile("ldmatrix.sync.aligned.m8n8.x4.trans.shared.b16 {%0,%1,%2,%3}, [%4];"
                 : "=r"(r[0]), "=r"(r[1]), "=r"(r[2]), "=r"(r[3]) : "r"(addr));
}
__device__ __forceinline__ void mma16816(float* c, const uint32_t* a,
                                         uint32_t b0, uint32_t b1)
{
    asm volatile(
        "mma.sync.aligned.m16n8k16.row.col.f32.f16.f16.f32 "
        "{%0,%1,%2,%3}, {%4,%5,%6,%7}, {%8,%9}, {%0,%1,%2,%3};"
        : "+f"(c[0]), "+f"(c[1]), "+f"(c[2]), "+f"(c[3])
        : "r"(a[0]), "r"(a[1]), "r"(a[2]), "r"(a[3]), "r"(b0), "r"(b1));
}
__device__ __forceinline__ float ex2f(float x)
{
    float r;
    asm("ex2.approx.f32 %0, %1;" : "=f"(r) : "f"(x));
    return r;
}
__device__ __forceinline__ uint32_t packh2(float x, float y)
{
    __half2 H = __floats2half2_rn(x, y);
    return *(uint32_t*)&H;
}

// ---------------------------------------------------------------------------
// GEMM-NT: C[m][n] = sum_k A[m][k] * W[n][k] (+ bias), fp16 1-term.
// CTA 256x128, GBK=64, 512 threads (16 warps, 8m x 2n), 3-stage cp.async.
// z=0 -> Q (QSCALE); z=1 -> K; z=2 -> V(+bv); z=3 -> fp32 out (+bo).
// ---------------------------------------------------------------------------
#define GBM 256
#define GBN 128
#define GBK 64
#define KSTR 72                         // padded k-stride (elements)
#define GAPL (256 * KSTR * 2)           // 36864 B  A plane
#define GBPL (128 * KSTR * 2)           // 18432 B  B plane
#define GBUF (GAPL + GBPL)              // 55296 B per stage
#define GSMEM (3 * GBUF)                // 165888 B
#define NKC (HID / GBK)                 // 12

__global__ __launch_bounds__(512, 1)
void gemm_mma_kernel(float* __restrict__ outp,
                     const float* __restrict__ bias_v,
                     const float* __restrict__ bias_o,
                     int z_base)
{
    extern __shared__ char smem[];
    const uint32_t sbase = smem_u32(smem);
    const int tid = threadIdx.x, wid = tid >> 5, lid = tid & 31;

    const int z  = z_base + blockIdx.z;
    const int n0 = blockIdx.x * GBN;
    const int m0 = blockIdx.y * GBM;

    const __half* gA = ((z == 3) ? g_oh : g_ah) + (size_t)m0 * HID;
    const __half* gB = g_wh + (size_t)z * WSZ + (size_t)n0 * HID;

    const int lrow = tid >> 3, lc8 = (tid & 7) * 8;   // 64 rows/pass

    const int wm = wid & 7, wn = wid >> 3;
    const int gr = lid >> 2, tq = (lid & 3) * 2;
    const int rA = (lid & 7) + ((lid >> 3) & 1) * 8;
    const int kA = (lid >> 4) * 8;
    const int rB = (lid & 7) + (lid >> 4) * 8;
    const int kB = ((lid >> 3) & 1) * 8;
    const uint32_t aoff = sbase + ((wm * 32 + rA) * KSTR + kA) * 2;
    const uint32_t boff = sbase + GAPL + ((wn * 64 + rB) * KSTR + kB) * 2;

    auto load_chunk = [&](int t, int stg) {
        const int ko = t * GBK;
        const uint32_t sb = sbase + stg * GBUF;
#pragma unroll
        for (int sub = 0; sub < 4; sub++) {          // A: 256 rows
            int row = lrow + sub * 64;
            cp16(sb + (row * KSTR + lc8) * 2, gA + (size_t)row * HID + ko + lc8);
        }
#pragma unroll
        for (int sub = 0; sub < 2; sub++) {          // B: 128 rows
            int row = lrow + sub * 64;
            cp16(sb + GAPL + (row * KSTR + lc8) * 2,
                 gB + (size_t)row * HID + ko + lc8);
        }
        cp_commit();
    };

    float c[2][8][4];
#pragma unroll
    for (int mi = 0; mi < 2; mi++)
#pragma unroll
        for (int ni = 0; ni < 8; ni++)
#pragma unroll
            for (int r = 0; r < 4; r++) c[mi][ni][r] = 0.f;

    load_chunk(0, 0);
    load_chunk(1, 1);

    int stg = 0, nstg = 2;
#pragma unroll 1
    for (int t = 0; t < NKC; t++) {
        cp_wait<1>();
        __syncthreads();
        if (t + 2 < NKC) load_chunk(t + 2, nstg);
        else             cp_commit();

        const uint32_t bb = stg * GBUF;
#pragma unroll
        for (int ks = 0; ks < 4; ks++) {
            uint32_t Ah[2][4];
            ldm4(Ah[0], aoff + bb + ks * 32);
            ldm4(Ah[1], aoff + bb + ks * 32 + 16 * KSTR * 2);
#pragma unroll
            for (int np = 0; np < 4; np++) {
                uint32_t Bh[4];
                ldm4(Bh, boff + bb + ks * 32 + np * 16 * KSTR * 2);
#pragma unroll
                for (int mi = 0; mi < 2; mi++) {
                    mma16816(c[mi][np * 2],     Ah[mi], Bh[0], Bh[1]);
                    mma16816(c[mi][np * 2 + 1], Ah[mi], Bh[2], Bh[3]);
                }
            }
        }
        stg = (stg == 2) ? 0 : stg + 1;
        nstg = (nstg == 2) ? 0 : nstg + 1;
    }

    // ---- epilogue ----
    if (z == 0) {          // Q: QSCALE (log2-domain) folded in
#pragma unroll
        for (int mi = 0; mi < 2; mi++) {
            const int row = m0 + wm * 32 + mi * 16 + gr;
#pragma unroll
            for (int ni = 0; ni < 8; ni++) {
                const int col = n0 + wn * 64 + ni * 8 + tq;
                *(uint32_t*)(g_qh + (size_t)row * HID + col) =
                    packh2(c[mi][ni][0] * QSCALE, c[mi][ni][1] * QSCALE);
                *(uint32_t*)(g_qh + (size_t)(row + 8) * HID + col) =
                    packh2(c[mi][ni][2] * QSCALE, c[mi][ni][3] * QSCALE);
            }
        }
    } else if (z < 3) {    // K or V
        __half* dst = (z == 1) ? g_kh : g_vh;
#pragma unroll
        for (int mi = 0; mi < 2; mi++) {
            const int row = m0 + wm * 32 + mi * 16 + gr;
#pragma unroll
            for (int ni = 0; ni < 8; ni++) {
                const int col = n0 + wn * 64 + ni * 8 + tq;
                float b0 = 0.f, b1 = 0.f;
                if (z == 2) { b0 = bias_v[col]; b1 = bias_v[col + 1]; }
                *(uint32_t*)(dst + (size_t)row * HID + col) =
                    packh2(c[mi][ni][0] + b0, c[mi][ni][1] + b1);
                *(uint32_t*)(dst + (size_t)(row + 8) * HID + col) =
                    packh2(c[mi][ni][2] + b0, c[mi][ni][3] + b1);
            }
        }
    } else {               // O projection: fp32 out + bo
#pragma unroll
        for (int mi = 0; mi < 2; mi++) {
            const int row = m0 + wm * 32 + mi * 16 + gr;
#pragma unroll
            for (int ni = 0; ni < 8; ni++) {
                const int col = n0 + wn * 64 + ni * 8 + tq;
                float b0 = bias_o[col], b1 = bias_o[col + 1];
                *(float2*)(outp + (size_t)row * HID + col) =
                    make_float2(c[mi][ni][0] + b0, c[mi][ni][1] + b1);
                *(float2*)(outp + (size_t)(row + 8) * HID + col) =
                    make_float2(c[mi][ni][2] + b0, c[mi][ni][3] + b1);
            }
        }
    }
}

// ---------------------------------------------------------------------------
// Tensor-core flash attention: Q,K,V,P,bias fp16; log2-domain softmax via
// MUFU ex2; K/V + bias in ONE double-buffered cp.async group, one barrier
// per chunk. CTA = 128 q-rows of one (b,h); 8 warps. O -> single fp16 plane.
// smem: Q 128x72 + 2 x [K 64x72, V 64x72, bias 128x72h] = 92160 B.
// ---------------------------------------------------------------------------
#define ATS 72
#define AQPL (128 * ATS * 2)    // 18432
#define AKPL (64 * ATS * 2)     // 9216
#define BPL  (128 * ATS * 2)    // 18432 (bias, fp16, stride 72)
#define KVBUF (2 * AKPL + BPL)  // 36864 per buffer
#define OFF_KV AQPL
#define ATTN_SMEM (AQPL + 2 * KVBUF)   // 92160

__global__ __launch_bounds__(256, 2)
void attn_mma_kernel()
{
    extern __shared__ char smem[];
    const uint32_t sbase = smem_u32(smem);
    const int tid = threadIdx.x, wid = tid >> 5, lid = tid & 31;
    const int qt = blockIdx.x, h = blockIdx.y, b = blockIdx.z;
    const int q0 = qt * 128;

    const int lrow = tid >> 3, lc8 = (tid & 7) * 8;
    const __half* ebase = g_eb + ((size_t)(b * NSEQ + q0)) * NSEQ;

    auto load_kvb = [&](int kc, int buf) {
        const size_t rb = (size_t)(b * NSEQ + kc * 64) * HID + h * DHEAD;
        const uint32_t sb = sbase + OFF_KV + buf * KVBUF;
#pragma unroll
        for (int sub = 0; sub < 2; sub++) {
            int row = lrow + sub * 32;
            cp16(sb + (row * ATS + lc8) * 2,        g_kh + rb + (size_t)row * HID + lc8);
            cp16(sb + AKPL + (row * ATS + lc8) * 2, g_vh + rb + (size_t)row * HID + lc8);
        }
        // bias: 128 rows x 64 halfs (8 segs of 8 halfs)
#pragma unroll
        for (int sub = 0; sub < 4; sub++) {
            int idx = tid + sub * 256;
            int row = idx >> 3, seg = idx & 7;
            cp16(sb + 2 * AKPL + (row * ATS + seg * 8) * 2,
                 ebase + (size_t)row * NSEQ + kc * 64 + seg * 8);
        }
        cp_commit();
    };

    // ---- load Q tile ----
    {
        const __half* qh = g_qh + (size_t)(b * NSEQ + q0) * HID + h * DHEAD;
#pragma unroll
        for (int l = 0; l < 4; l++) {
            int row = lrow + l * 32;
            cp16(sbase + (row * ATS + lc8) * 2, qh + (size_t)row * HID + lc8);
        }
        cp_commit();
    }
    load_kvb(0, 0);

    const int gr = lid >> 2, tq = (lid & 3) * 2;
    const int rA = (lid & 7) + ((lid >> 3) & 1) * 8;
    const int kA = (lid >> 4) * 8;
    const int rB = (lid & 7) + (lid >> 4) * 8;
    const int kB = ((lid >> 3) & 1) * 8;
    const uint32_t aQh = sbase + ((wid * 16 + rA) * ATS + kA) * 2;
    const uint32_t oK  = (rB * ATS + kB) * 2;
    const uint32_t oV  = ((lid & 15) * ATS + (lid >> 4) * 8) * 2;
    const uint32_t oB0 = 2 * AKPL + ((wid * 16 + gr) * ATS + tq) * 2;
    const uint32_t oB1 = oB0 + 8 * ATS * 2;

    float acc[8][4];
#pragma unroll
    for (int j = 0; j < 8; j++)
#pragma unroll
        for (int r = 0; r < 4; r++) acc[j][r] = 0.f;
    float mr0 = -1e30f, mr1 = -1e30f, rs0 = 0.f, rs1 = 0.f;
    int nz0 = 0, nz1 = 0;

#pragma unroll 1
    for (int kc = 0; kc < 8; kc++) {
        cp_wait<0>();      // K/V/bias chunk kc (+ Q first iter) resident
        __syncthreads();   // separates last iter's reads from this iter's loads
        if (kc + 1 < 8) load_kvb(kc + 1, (kc + 1) & 1);

        const uint32_t kvb = sbase + OFF_KV + (kc & 1) * KVBUF;
        const uint32_t aK = kvb + oK;
        const uint32_t aV = kvb + AKPL + oV;
        const char* bsm = (const char*)smem + (kvb - sbase);

        // ---- S = Q K^T (log2 domain) ----
        float c[8][4];
#pragma unroll
        for (int j = 0; j < 8; j++)
#pragma unroll
            for (int r = 0; r < 4; r++) c[j][r] = 0.f;

#pragma unroll
        for (int ks = 0; ks < 4; ks++) {
            uint32_t Qh[4];
            ldm4(Qh, aQh + ks * 32);
#pragma unroll
            for (int np = 0; np < 4; np++) {
                uint32_t Kh[4];
                ldm4(Kh, aK + ks * 32 + np * 16 * ATS * 2);
                mma16816(c[np * 2],     Qh, Kh[0], Kh[1]);
                mma16816(c[np * 2 + 1], Qh, Kh[2], Kh[3]);
            }
        }

        // ---- add bias (fp16 smem, x LOG2E), online softmax (log2 domain) --
        float mc0 = -1e30f, mc1 = -1e30f;
        int n0 = 0, n1 = 0;
#pragma unroll
        for (int j = 0; j < 8; j++) {
            float2 b0 = __half22float2(*(const __half2*)(bsm + oB0 + j * 16));
            float2 b1 = __half22float2(*(const __half2*)(bsm + oB1 + j * 16));
            c[j][0] = fmaf(b0.x, LOG2E_F, c[j][0]);
            c[j][1] = fmaf(b0.y, LOG2E_F, c[j][1]);
            c[j][2] = fmaf(b1.x, LOG2E_F, c[j][2]);
            c[j][3] = fmaf(b1.y, LOG2E_F, c[j][3]);
            mc0 = fmaxf(mc0, fmaxf(c[j][0], c[j][1]));
            mc1 = fmaxf(mc1, fmaxf(c[j][2], c[j][3]));
            n0 |= (c[j][0] != 0.f) | (c[j][1] != 0.f);
            n1 |= (c[j][2] != 0.f) | (c[j][3] != 0.f);
        }
#pragma unroll
        for (int o = 1; o < 4; o <<= 1) {
            mc0 = fmaxf(mc0, __shfl_xor_sync(0xffffffffu, mc0, o));
            mc1 = fmaxf(mc1, __shfl_xor_sync(0xffffffffu, mc1, o));
            n0 |= __shfl_xor_sync(0xffffffffu, n0, o);
            n1 |= __shfl_xor_sync(0xffffffffu, n1, o);
        }
        nz0 |= n0; nz1 |= n1;
        float mn0 = fmaxf(mr0, mc0), mn1 = fmaxf(mr1, mc1);
        float cr0 = ex2f(mr0 - mn0);
        float cr1 = ex2f(mr1 - mn1);
        mr0 = mn0; mr1 = mn1;

        float s0 = 0.f, s1 = 0.f;
#pragma unroll
        for (int j = 0; j < 8; j++) {
            c[j][0] = ex2f(c[j][0] - mn0);
            c[j][1] = ex2f(c[j][1] - mn0);
            c[j][2] = ex2f(c[j][2] - mn1);
            c[j][3] = ex2f(c[j][3] - mn1);
            s0 += c[j][0] + c[j][1];
            s1 += c[j][2] + c[j][3];
        }
#pragma unroll
        for (int o = 1; o < 4; o <<= 1) {
            s0 += __shfl_xor_sync(0xffffffffu, s0, o);
            s1 += __shfl_xor_sync(0xffffffffu, s1, o);
        }
        rs0 = rs0 * cr0 + s0;
        rs1 = rs1 * cr1 + s1;
#pragma unroll
        for (int j = 0; j < 8; j++) {
            acc[j][0] *= cr0; acc[j][1] *= cr0;
            acc[j][2] *= cr1; acc[j][3] *= cr1;
        }

        // ---- acc += P V (P single fp16) ----
#pragma unroll
        for (int ks = 0; ks < 4; ks++) {
            uint32_t Ph[4];
            Ph[0] = packh2(c[2 * ks][0],     c[2 * ks][1]);
            Ph[1] = packh2(c[2 * ks][2],     c[2 * ks][3]);
            Ph[2] = packh2(c[2 * ks + 1][0], c[2 * ks + 1][1]);
            Ph[3] = packh2(c[2 * ks + 1][2], c[2 * ks + 1][3]);
#pragma unroll
            for (int np = 0; np < 4; np++) {
                uint32_t Vh[4];
                ldm4t(Vh, aV + ks * 16 * ATS * 2 + np * 32);
                mma16816(acc[np * 2],     Ph, Vh[0], Vh[1]);
                mma16816(acc[np * 2 + 1], Ph, Vh[2], Vh[3]);
            }
        }
    }

    // ---- epilogue: normalize (pad-mask) and store O (single fp16 plane) ----
    const float i0 = nz0 ? (1.f / rs0) : 0.f;
    const float i1 = nz1 ? (1.f / rs1) : 0.f;
    __half* oh = g_oh + (size_t)(b * NSEQ + q0 + wid * 16) * HID + h * DHEAD;
#pragma unroll
    for (int j = 0; j < 8; j++) {
        const int col = j * 8 + tq;
        *(uint32_t*)(oh + (size_t)gr * HID + col) =
            packh2(acc[j][0] * i0, acc[j][1] * i0);
        *(uint32_t*)(oh + (size_t)(gr + 8) * HID + col) =
            packh2(acc[j][2] * i1, acc[j][3] * i1);
    }
}

// ---------------------------------------------------------------------------
// inputs: x, encoding_bias, Wq, Wk, Wv, bv, Wo, bo
// ---------------------------------------------------------------------------
extern "C" void kernel_launch(void* const* d_in, const int* in_sizes, int n_in,
                              void* d_out, int out_size)
{
    const float* x  = (const float*)d_in[0];
    const float* eb = (const float*)d_in[1];
    const float* Wq = (const float*)d_in[2];
    const float* Wk = (const float*)d_in[3];
    const float* Wv = (const float*)d_in[4];
    const float* bv = (const float*)d_in[5];
    const float* Wo = (const float*)d_in[6];
    const float* bo = (const float*)d_in[7];
    float* out = (float*)d_out;

    cudaFuncSetAttribute(attn_mma_kernel,
                         cudaFuncAttributeMaxDynamicSharedMemorySize, ATTN_SMEM);
    cudaFuncSetAttribute(gemm_mma_kernel,
                         cudaFuncAttributeMaxDynamicSharedMemorySize, GSMEM);

    const int nx4 = MTOT * HID / 4;
    const int nw4 = WSZ / 4;
    const int nb4 = 16 * NSEQ * NSEQ / 4;

    conv_round_x<<<(nx4 + 255) / 256, 256>>>(x, nx4);
    conv_round_eb<<<(nb4 + 255) / 256, 256>>>(eb, nb4);
    conv_w4<<<dim3((nw4 + 255) / 256, 4), 256>>>(Wq, Wk, Wv, Wo, nw4);

    gemm_mma_kernel<<<dim3(HID / GBN, MTOT / GBM, 3), 512, GSMEM>>>(
        nullptr, bv, nullptr, 0);                                   // Q,K,V

    attn_mma_kernel<<<dim3(4, NHEAD, 16), 256, ATTN_SMEM>>>();      // O

    gemm_mma_kernel<<<dim3(HID / GBN, MTOT / GBM, 1), 512, GSMEM>>>(
        out, nullptr, bo, 3);                                       // O proj
}